// round 4
// baseline (speedup 1.0000x reference)
#include <cuda_runtime.h>
#include <cstdint>
#include <math.h>

#define BATCH 16
#define PP    8192
#define NTOT  (BATCH*PP)     // 131072
#define KNN   4
#define CDIM  256
#define HEADS 4
#define FDIM  64
#define GRID  32
#define NCELL (GRID*GRID)    // 1024
#define NEG_SLOPE 0.2f

// ------------------- scratch (__device__ globals, no mallocs) -------------------
__device__ int    d_cnt[BATCH*NCELL];
__device__ int    d_start[BATCH*(NCELL+1)];
__device__ int    d_cur[BATCH*NCELL];
__device__ int    d_sorted[NTOT];       // sorted pos -> orig local id
__device__ float2 d_sc[NTOT];           // coords in sorted order
__device__ int    d_nbr[NTOT*KNN];      // neighbors in SORTED space
__device__ float  d_h[NTOT*CDIM];       // GEMM output (sorted space)
__device__ float  d_y[NTOT*CDIM];       // permuted input / agg output (sorted space)
__device__ float  d_as[NTOT*HEADS];
__device__ float  d_ad[NTOT*HEADS];
__device__ float  d_h2[NTOT*2];
__device__ float  d_a2s[NTOT];
__device__ float  d_a2d[NTOT];

__device__ __forceinline__ uint32_t f32_to_tf32(float f) {
    uint32_t o;
    asm("cvt.rna.tf32.f32 %0, %1;" : "=r"(o) : "f"(f));
    return o;
}

// ------------------------------- kNN pipeline ----------------------------------
__global__ void zero_cnt_kernel() {
    int i = blockIdx.x * blockDim.x + threadIdx.x;
    if (i < BATCH*NCELL) d_cnt[i] = 0;
}
__device__ __forceinline__ int cell_of(float v) {
    int c = (int)(v * GRID);
    return min(GRID-1, max(0, c));
}
__global__ void count_kernel(const float* __restrict__ coords) {
    int i = blockIdx.x * blockDim.x + threadIdx.x;
    if (i >= NTOT) return;
    float2 c = ((const float2*)coords)[i];
    int b = i >> 13;
    atomicAdd(&d_cnt[b*NCELL + cell_of(c.y)*GRID + cell_of(c.x)], 1);
}
__global__ void scan_kernel() {
    __shared__ int s[NCELL];
    int b = blockIdx.x, t = threadIdx.x;
    int v = d_cnt[b*NCELL + t];
    s[t] = v;
    __syncthreads();
    for (int off = 1; off < NCELL; off <<= 1) {
        int add = (t >= off) ? s[t-off] : 0;
        __syncthreads();
        s[t] += add;
        __syncthreads();
    }
    int excl = s[t] - v;
    d_start[b*(NCELL+1) + t] = excl;
    d_cur[b*NCELL + t]       = excl;
    if (t == NCELL-1) d_start[b*(NCELL+1) + NCELL] = s[t];
}
__global__ void scatter_kernel(const float* __restrict__ coords) {
    int i = blockIdx.x * blockDim.x + threadIdx.x;
    if (i >= NTOT) return;
    float2 c = ((const float2*)coords)[i];
    int b = i >> 13, p = i & (PP-1);
    int cell = cell_of(c.y)*GRID + cell_of(c.x);
    int pos = atomicAdd(&d_cur[b*NCELL + cell], 1);
    d_sorted[b*PP + pos] = p;
    d_sc[b*PP + pos] = c;
}

// contiguous scan over sorted coords; neighbor ids are sorted-space globals
__device__ __forceinline__ void scan_cell(int b, int cell, float qx, float qy,
                                          float bd[4], int bi[4]) {
    int s0 = d_start[b*(NCELL+1) + cell];
    int s1 = d_start[b*(NCELL+1) + cell + 1];
    int base = b << 13;
    for (int j = s0; j < s1; j++) {
        float2 c2 = d_sc[base + j];
        float dx = c2.x - qx, dy = c2.y - qy;
        float d2 = dx*dx + dy*dy;
        if (d2 < bd[3]) {
            int gi = base + j;
            if (d2 < bd[2]) { bd[3]=bd[2]; bi[3]=bi[2];
                if (d2 < bd[1]) { bd[2]=bd[1]; bi[2]=bi[1];
                    if (d2 < bd[0]) { bd[1]=bd[0]; bi[1]=bi[0]; bd[0]=d2; bi[0]=gi; }
                    else            { bd[1]=d2; bi[1]=gi; }
                } else { bd[2]=d2; bi[2]=gi; }
            } else { bd[3]=d2; bi[3]=gi; }
        }
    }
}
__global__ void knn_kernel() {
    int n = blockIdx.x * blockDim.x + threadIdx.x;   // sorted-space id
    if (n >= NTOT) return;
    int b = n >> 13;
    float2 q = d_sc[n];
    int cx = cell_of(q.x), cy = cell_of(q.y);
    float bd[4] = {1e30f, 1e30f, 1e30f, 1e30f};
    int   bi[4] = {n, n, n, n};
    int x0 = max(0, cx-1), x1 = min(GRID-1, cx+1);
    int y0 = max(0, cy-1), y1 = min(GRID-1, cy+1);
    for (int yy = y0; yy <= y1; yy++)
        for (int xx = x0; xx <= x1; xx++)
            scan_cell(b, yy*GRID + xx, q.x, q.y, bd, bi);
    const float hcell = 1.0f / GRID;
    int r = 1;
    while (true) {
        float bound = r * hcell;
        if (bd[3] <= bound*bound) break;
        bool full = (cx-r <= 0) && (cy-r <= 0) && (cx+r >= GRID-1) && (cy+r >= GRID-1);
        if (full) break;
        r++;
        int rx0 = cx-r, rx1 = cx+r, ry0 = cy-r, ry1 = cy+r;
        int cxl = max(0, rx0), cxr = min(GRID-1, rx1);
        if (ry0 >= 0)      for (int xx = cxl; xx <= cxr; xx++) scan_cell(b, ry0*GRID + xx, q.x, q.y, bd, bi);
        if (ry1 <= GRID-1) for (int xx = cxl; xx <= cxr; xx++) scan_cell(b, ry1*GRID + xx, q.x, q.y, bd, bi);
        int cyl = max(0, ry0+1), cyr = min(GRID-1, ry1-1);
        if (rx0 >= 0)      for (int yy = cyl; yy <= cyr; yy++) scan_cell(b, yy*GRID + rx0, q.x, q.y, bd, bi);
        if (rx1 <= GRID-1) for (int yy = cyl; yy <= cyr; yy++) scan_cell(b, yy*GRID + rx1, q.x, q.y, bd, bi);
    }
    #pragma unroll
    for (int k = 0; k < KNN; k++) d_nbr[n*KNN + k] = bi[k];
}

// ----------------- permute x into sorted order (one warp per node) -------------
__global__ void perm_kernel(const float* __restrict__ x, float* __restrict__ xp) {
    int w = (blockIdx.x * blockDim.x + threadIdx.x) >> 5;
    int lane = threadIdx.x & 31;
    if (w >= NTOT) return;
    int orig = ((w >> 13) << 13) + d_sorted[w];
    const float4* src = (const float4*)(x + (size_t)orig*CDIM);
    float4* dst = (float4*)(xp + (size_t)w*CDIM);
    dst[lane]      = src[lane];
    dst[lane + 32] = src[lane + 32];
}

// ---------------- tf32 mma.sync GEMM: C[N,256] = A[N,256] @ W[256,256] ----------
#define BK 32
#define ASTRIDE 132
#define ABUF_BYTES (BK*ASTRIDE*4)
#define SM_TOTAL (4*ABUF_BYTES)

__device__ __forceinline__ void mma_tf32(float d[4], const uint32_t a[4], const uint32_t b[2]) {
    asm volatile(
        "mma.sync.aligned.m16n8k8.row.col.f32.tf32.tf32.f32 "
        "{%0,%1,%2,%3}, {%4,%5,%6,%7}, {%8,%9}, {%0,%1,%2,%3};"
        : "+f"(d[0]), "+f"(d[1]), "+f"(d[2]), "+f"(d[3])
        : "r"(a[0]), "r"(a[1]), "r"(a[2]), "r"(a[3]), "r"(b[0]), "r"(b[1]));
}

__global__ void __launch_bounds__(256, 1) tc_gemm_kernel(
    const float* __restrict__ A, const float* __restrict__ W,
    float* __restrict__ Hout)
{
    extern __shared__ char smem[];
    float* Asb[2] = { (float*)smem,                  (float*)(smem + ABUF_BYTES) };
    float* Bsb[2] = { (float*)(smem + 2*ABUF_BYTES), (float*)(smem + 3*ABUF_BYTES) };

    int tid = threadIdx.x;
    int wid = tid >> 5, lane = tid & 31;
    int lm = lane >> 2, lk = lane & 3;
    int wm = wid & 1, wn = wid >> 1;
    int rowBase = blockIdx.y * 128;
    int colBase = blockIdx.x * 128;

    float acc[4][4][4];
    #pragma unroll
    for (int mt = 0; mt < 4; mt++)
        #pragma unroll
        for (int nt = 0; nt < 4; nt++)
            #pragma unroll
            for (int i = 0; i < 4; i++) acc[mt][nt][i] = 0.f;

    float4 ra[4], rb[4];

    auto load_tile = [&](int kk) {
        #pragma unroll
        for (int i = 0; i < 4; i++) {
            int idx = tid + i*256;
            int r = idx >> 3, c4 = idx & 7;
            ra[i] = *(const float4*)(A + (size_t)(rowBase + r)*CDIM + kk + c4*4);
        }
        #pragma unroll
        for (int i = 0; i < 4; i++) {
            int idx = tid + i*256;
            int k = idx >> 5, n4 = idx & 31;
            rb[i] = *(const float4*)(W + (size_t)(kk + k)*CDIM + colBase + n4*4);
        }
    };
    auto store_tile = [&](int s) {
        float* As = Asb[s];
        float* Bs = Bsb[s];
        #pragma unroll
        for (int i = 0; i < 4; i++) {
            int idx = tid + i*256;
            int r = idx >> 3, c4 = idx & 7;
            As[(c4*4+0)*ASTRIDE + r] = __uint_as_float(f32_to_tf32(ra[i].x));
            As[(c4*4+1)*ASTRIDE + r] = __uint_as_float(f32_to_tf32(ra[i].y));
            As[(c4*4+2)*ASTRIDE + r] = __uint_as_float(f32_to_tf32(ra[i].z));
            As[(c4*4+3)*ASTRIDE + r] = __uint_as_float(f32_to_tf32(ra[i].w));
        }
        #pragma unroll
        for (int i = 0; i < 4; i++) {
            int idx = tid + i*256;
            int k = idx >> 5, n4 = idx & 31;
            float4 t;
            t.x = __uint_as_float(f32_to_tf32(rb[i].x));
            t.y = __uint_as_float(f32_to_tf32(rb[i].y));
            t.z = __uint_as_float(f32_to_tf32(rb[i].z));
            t.w = __uint_as_float(f32_to_tf32(rb[i].w));
            *(float4*)(Bs + k*ASTRIDE + n4*4) = t;
        }
    };
    auto compute = [&](int s) {
        const float* As = Asb[s];
        const float* Bs = Bsb[s];
        #pragma unroll
        for (int ks = 0; ks < 4; ks++) {
            int k0 = ks*8;
            uint32_t af[4][4], bf[4][2];
            #pragma unroll
            for (int mt = 0; mt < 4; mt++) {
                int m0 = wm*64 + mt*16 + lm;
                af[mt][0] = __float_as_uint(As[(k0+lk)*ASTRIDE   + m0]);
                af[mt][1] = __float_as_uint(As[(k0+lk)*ASTRIDE   + m0 + 8]);
                af[mt][2] = __float_as_uint(As[(k0+lk+4)*ASTRIDE + m0]);
                af[mt][3] = __float_as_uint(As[(k0+lk+4)*ASTRIDE + m0 + 8]);
            }
            #pragma unroll
            for (int nt = 0; nt < 4; nt++) {
                int n0 = wn*32 + nt*8 + lm;
                bf[nt][0] = __float_as_uint(Bs[(k0+lk)*ASTRIDE   + n0]);
                bf[nt][1] = __float_as_uint(Bs[(k0+lk+4)*ASTRIDE + n0]);
            }
            #pragma unroll
            for (int mt = 0; mt < 4; mt++)
                #pragma unroll
                for (int nt = 0; nt < 4; nt++)
                    mma_tf32(acc[mt][nt], af[mt], bf[nt]);
        }
    };

    load_tile(0);
    store_tile(0);
    __syncthreads();
    #pragma unroll 1
    for (int t = 0; t < 8; t++) {
        if (t < 7) load_tile((t+1)*BK);
        compute(t & 1);
        if (t < 7) {
            store_tile((t+1) & 1);
            __syncthreads();
        }
    }

    #pragma unroll
    for (int mt = 0; mt < 4; mt++) {
        int row = rowBase + wm*64 + mt*16 + lm;
        #pragma unroll
        for (int nt = 0; nt < 4; nt++) {
            int col = colBase + wn*32 + nt*8 + lk*2;
            *(float2*)(Hout + (size_t)row*CDIM + col)     = make_float2(acc[mt][nt][0], acc[mt][nt][1]);
            *(float2*)(Hout + (size_t)(row+8)*CDIM + col) = make_float2(acc[mt][nt][2], acc[mt][nt][3]);
        }
    }
}

// ----------------------- attention scalars: asrc/adst --------------------------
__global__ void att_kernel(const float* __restrict__ Hbuf,
                           const float* __restrict__ a_src,
                           const float* __restrict__ a_dst) {
    int wid  = (blockIdx.x * blockDim.x + threadIdx.x) >> 5;
    int lane = threadIdx.x & 31;
    if (wid >= NTOT) return;
    const float4* hp = (const float4*)&Hbuf[(size_t)wid * CDIM];
    float x8[8], s8[8], t8[8];
    *(float4*)&x8[0] = hp[lane*2];   *(float4*)&x8[4] = hp[lane*2+1];
    *(float4*)&s8[0] = ((const float4*)a_src)[lane*2];
    *(float4*)&s8[4] = ((const float4*)a_src)[lane*2+1];
    *(float4*)&t8[0] = ((const float4*)a_dst)[lane*2];
    *(float4*)&t8[4] = ((const float4*)a_dst)[lane*2+1];
    float ps = 0.f, pd = 0.f;
    #pragma unroll
    for (int j = 0; j < 8; j++) { ps += x8[j]*s8[j]; pd += x8[j]*t8[j]; }
    #pragma unroll
    for (int off = 4; off > 0; off >>= 1) {
        ps += __shfl_down_sync(0xffffffffu, ps, off);
        pd += __shfl_down_sync(0xffffffffu, pd, off);
    }
    if ((lane & 7) == 0) {
        int h = lane >> 3;
        d_as[wid*HEADS + h] = ps;
        d_ad[wid*HEADS + h] = pd;
    }
}

// ---------------------- softmax-attention aggregation --------------------------
__global__ void agg_kernel(const float* __restrict__ Hbuf,
                           const float* __restrict__ bias,
                           float* __restrict__ Out, int apply_elu) {
    int tid = threadIdx.x;
    int n = blockIdx.x*4 + (tid >> 6);
    int t = tid & 63;
    int nb[4];
    #pragma unroll
    for (int k = 0; k < 4; k++) nb[k] = d_nbr[n*KNN + k];
    float alpha[4][4];
    #pragma unroll
    for (int h = 0; h < HEADS; h++) {
        float ad = d_ad[n*HEADS + h];
        float e[4], m = -1e30f;
        #pragma unroll
        for (int k = 0; k < 4; k++) {
            float v = d_as[nb[k]*HEADS + h] + ad;
            v = v > 0.f ? v : NEG_SLOPE * v;
            e[k] = v; m = fmaxf(m, v);
        }
        float s = 0.f;
        #pragma unroll
        for (int k = 0; k < 4; k++) { e[k] = __expf(e[k] - m); s += e[k]; }
        float inv = 1.f / s;
        #pragma unroll
        for (int k = 0; k < 4; k++) alpha[k][h] = e[k] * inv;
    }
    #pragma unroll
    for (int h = 0; h < HEADS; h++) {
        float acc = bias[h*FDIM + t];
        #pragma unroll
        for (int k = 0; k < 4; k++)
            acc += alpha[k][h] * Hbuf[(size_t)nb[k]*CDIM + h*FDIM + t];
        if (apply_elu) acc = acc > 0.f ? acc : (__expf(acc) - 1.f);
        Out[(size_t)n*CDIM + h*FDIM + t] = acc;
    }
}

// --------------------------- layer 2 (256 -> 2) --------------------------------
__global__ void l2gemm_kernel(const float* __restrict__ X,
                              const float* __restrict__ W2,
                              const float* __restrict__ as2,
                              const float* __restrict__ ad2) {
    int wid  = (blockIdx.x * blockDim.x + threadIdx.x) >> 5;
    int lane = threadIdx.x & 31;
    if (wid >= NTOT) return;
    const float4* xp = (const float4*)&X[(size_t)wid * CDIM];
    float x8[8];
    *(float4*)&x8[0] = xp[lane*2];  *(float4*)&x8[4] = xp[lane*2+1];
    float d0 = 0.f, d1 = 0.f;
    #pragma unroll
    for (int j = 0; j < 8; j++) {
        int f = lane*8 + j;
        d0 += x8[j] * W2[f*2];
        d1 += x8[j] * W2[f*2 + 1];
    }
    #pragma unroll
    for (int off = 16; off > 0; off >>= 1) {
        d0 += __shfl_down_sync(0xffffffffu, d0, off);
        d1 += __shfl_down_sync(0xffffffffu, d1, off);
    }
    if (lane == 0) {
        d_h2[wid*2]   = d0;
        d_h2[wid*2+1] = d1;
        d_a2s[wid] = d0*as2[0] + d1*as2[1];
        d_a2d[wid] = d0*ad2[0] + d1*ad2[1];
    }
}

__global__ void final_kernel(const float* __restrict__ b2, float* __restrict__ out) {
    int n = blockIdx.x * blockDim.x + threadIdx.x;
    if (n >= NTOT) return;
    int nb[4];
    #pragma unroll
    for (int k = 0; k < 4; k++) nb[k] = d_nbr[n*KNN + k];
    float ad = d_a2d[n];
    float e[4], m = -1e30f;
    #pragma unroll
    for (int k = 0; k < 4; k++) {
        float v = d_a2s[nb[k]] + ad;
        v = v > 0.f ? v : NEG_SLOPE * v;
        e[k] = v; m = fmaxf(m, v);
    }
    float s = 0.f;
    #pragma unroll
    for (int k = 0; k < 4; k++) { e[k] = __expf(e[k] - m); s += e[k]; }
    float inv = 1.f / s;
    float o0 = 0.f, o1 = 0.f;
    #pragma unroll
    for (int k = 0; k < 4; k++) {
        float a = e[k] * inv;
        o0 += a * d_h2[nb[k]*2];
        o1 += a * d_h2[nb[k]*2 + 1];
    }
    int orig = ((n >> 13) << 13) + d_sorted[n];   // un-permute
    out[orig*2]     = o0 + b2[0];
    out[orig*2 + 1] = o1 + b2[1];
}

// --------------------------------- launch --------------------------------------
extern "C" void kernel_launch(void* const* d_in, const int* in_sizes, int n_in,
                              void* d_out, int out_size) {
    const float* coords   = (const float*)d_in[0];
    const float* x        = (const float*)d_in[1];
    const float* W0       = (const float*)d_in[2];
    const float* att_src0 = (const float*)d_in[3];
    const float* att_dst0 = (const float*)d_in[4];
    const float* b0       = (const float*)d_in[5];
    const float* W1       = (const float*)d_in[6];
    const float* att_src1 = (const float*)d_in[7];
    const float* att_dst1 = (const float*)d_in[8];
    const float* b1       = (const float*)d_in[9];
    const float* W2       = (const float*)d_in[10];
    const float* att_src2 = (const float*)d_in[11];
    const float* att_dst2 = (const float*)d_in[12];
    const float* b2       = (const float*)d_in[13];
    float* out = (float*)d_out;

    float *hp, *yp;
    cudaGetSymbolAddress((void**)&hp, d_h);
    cudaGetSymbolAddress((void**)&yp, d_y);

    cudaFuncSetAttribute(tc_gemm_kernel, cudaFuncAttributeMaxDynamicSharedMemorySize, SM_TOTAL);

    // kNN graph build (sorted space)
    zero_cnt_kernel<<<64, 256>>>();
    count_kernel<<<512, 256>>>(coords);
    scan_kernel<<<BATCH, 1024>>>();
    scatter_kernel<<<512, 256>>>(coords);
    knn_kernel<<<512, 256>>>();

    // permute x into sorted order (into d_y)
    perm_kernel<<<NTOT/8, 256>>>(x, yp);

    dim3 ggrid(CDIM/128, NTOT/128);   // (2, 1024)

    // Layer 0  (y=x_perm -> h -> y)
    tc_gemm_kernel<<<ggrid, 256, SM_TOTAL>>>(yp, W0, hp);
    att_kernel<<<NTOT/8, 256>>>(hp, att_src0, att_dst0);
    agg_kernel<<<NTOT/4, 256>>>(hp, b0, yp, 1);

    // Layer 1
    tc_gemm_kernel<<<ggrid, 256, SM_TOTAL>>>(yp, W1, hp);
    att_kernel<<<NTOT/8, 256>>>(hp, att_src1, att_dst1);
    agg_kernel<<<NTOT/4, 256>>>(hp, b1, yp, 1);

    // Layer 2
    l2gemm_kernel<<<NTOT/8, 256>>>(yp, W2, att_src2, att_dst2);
    final_kernel<<<512, 256>>>(b2, out);
}

// round 5
// speedup vs baseline: 1.7664x; 1.7664x over previous
#include <cuda_runtime.h>
#include <cuda_fp16.h>
#include <cstdint>
#include <math.h>

#define BATCH 16
#define PP    8192
#define NTOT  (BATCH*PP)     // 131072
#define KNN   4
#define CDIM  256
#define HEADS 4
#define FDIM  64
#define GRID  32
#define NCELL (GRID*GRID)    // 1024
#define NEG_SLOPE 0.2f

// ------------------- scratch (__device__ globals, no mallocs) -------------------
__device__ int      d_cnt[BATCH*NCELL];
__device__ int      d_start[BATCH*(NCELL+1)];
__device__ int      d_cur[BATCH*NCELL];
__device__ int      d_sorted[NTOT];
__device__ float2   d_sc[NTOT];
__device__ int      d_nbr[NTOT*KNN];
__device__ float    d_h[NTOT*CDIM];      // GEMM output (fp32, sorted space)
__device__ float    d_y[NTOT*CDIM];      // layer-1 agg output (fp32, for l2gemm)
__device__ __half   d_ah[NTOT*CDIM];     // fp16 GEMM input (perm x / layer-0 agg out)
__device__ float    d_as[NTOT*HEADS];
__device__ float    d_ad[NTOT*HEADS];
__device__ float    d_h2[NTOT*2];
__device__ float    d_a2s[NTOT];
__device__ float    d_a2d[NTOT];
__device__ uint32_t d_wp0[128*256];      // W0 packed: half2 pairs along k, [k2][n]
__device__ uint32_t d_wp1[128*256];

// ----------------------------- PTX helpers --------------------------------------
__device__ __forceinline__ uint32_t smem_u32(const void* p) {
    uint32_t a;
    asm("{ .reg .u64 t; cvta.to.shared.u64 t, %1; cvt.u32.u64 %0, t; }" : "=r"(a) : "l"(p));
    return a;
}
__device__ __forceinline__ void cp16(uint32_t dst, const void* src) {
    asm volatile("cp.async.cg.shared.global [%0], [%1], 16;" :: "r"(dst), "l"(src));
}
#define CP_COMMIT() asm volatile("cp.async.commit_group;" ::: "memory")
#define CP_WAIT(N)  asm volatile("cp.async.wait_group %0;" :: "n"(N) : "memory")

__device__ __forceinline__ void mma_f16(float d[4], const uint32_t a[4], const uint32_t b[2]) {
    asm volatile(
        "mma.sync.aligned.m16n8k16.row.col.f32.f16.f16.f32 "
        "{%0,%1,%2,%3}, {%4,%5,%6,%7}, {%8,%9}, {%0,%1,%2,%3};"
        : "+f"(d[0]), "+f"(d[1]), "+f"(d[2]), "+f"(d[3])
        : "r"(a[0]), "r"(a[1]), "r"(a[2]), "r"(a[3]), "r"(b[0]), "r"(b[1]));
}

// ------------------------------- kNN pipeline ----------------------------------
__global__ void zero_cnt_kernel() {
    int i = blockIdx.x * blockDim.x + threadIdx.x;
    if (i < BATCH*NCELL) d_cnt[i] = 0;
}
__device__ __forceinline__ int cell_of(float v) {
    int c = (int)(v * GRID);
    return min(GRID-1, max(0, c));
}
__global__ void count_kernel(const float* __restrict__ coords) {
    int i = blockIdx.x * blockDim.x + threadIdx.x;
    if (i >= NTOT) return;
    float2 c = ((const float2*)coords)[i];
    int b = i >> 13;
    atomicAdd(&d_cnt[b*NCELL + cell_of(c.y)*GRID + cell_of(c.x)], 1);
}
__global__ void scan_kernel() {
    __shared__ int s[NCELL];
    int b = blockIdx.x, t = threadIdx.x;
    int v = d_cnt[b*NCELL + t];
    s[t] = v;
    __syncthreads();
    for (int off = 1; off < NCELL; off <<= 1) {
        int add = (t >= off) ? s[t-off] : 0;
        __syncthreads();
        s[t] += add;
        __syncthreads();
    }
    int excl = s[t] - v;
    d_start[b*(NCELL+1) + t] = excl;
    d_cur[b*NCELL + t]       = excl;
    if (t == NCELL-1) d_start[b*(NCELL+1) + NCELL] = s[t];
}
__global__ void scatter_kernel(const float* __restrict__ coords) {
    int i = blockIdx.x * blockDim.x + threadIdx.x;
    if (i >= NTOT) return;
    float2 c = ((const float2*)coords)[i];
    int b = i >> 13, p = i & (PP-1);
    int cell = cell_of(c.y)*GRID + cell_of(c.x);
    int pos = atomicAdd(&d_cur[b*NCELL + cell], 1);
    d_sorted[b*PP + pos] = p;
    d_sc[b*PP + pos] = c;
}
__device__ __forceinline__ void scan_cell(int b, int cell, float qx, float qy,
                                          float bd[4], int bi[4]) {
    int s0 = d_start[b*(NCELL+1) + cell];
    int s1 = d_start[b*(NCELL+1) + cell + 1];
    int base = b << 13;
    for (int j = s0; j < s1; j++) {
        float2 c2 = d_sc[base + j];
        float dx = c2.x - qx, dy = c2.y - qy;
        float d2 = dx*dx + dy*dy;
        if (d2 < bd[3]) {
            int gi = base + j;
            if (d2 < bd[2]) { bd[3]=bd[2]; bi[3]=bi[2];
                if (d2 < bd[1]) { bd[2]=bd[1]; bi[2]=bi[1];
                    if (d2 < bd[0]) { bd[1]=bd[0]; bi[1]=bi[0]; bd[0]=d2; bi[0]=gi; }
                    else            { bd[1]=d2; bi[1]=gi; }
                } else { bd[2]=d2; bi[2]=gi; }
            } else { bd[3]=d2; bi[3]=gi; }
        }
    }
}
__global__ void knn_kernel() {
    int n = blockIdx.x * blockDim.x + threadIdx.x;
    if (n >= NTOT) return;
    int b = n >> 13;
    float2 q = d_sc[n];
    int cx = cell_of(q.x), cy = cell_of(q.y);
    float bd[4] = {1e30f, 1e30f, 1e30f, 1e30f};
    int   bi[4] = {n, n, n, n};
    int x0 = max(0, cx-1), x1 = min(GRID-1, cx+1);
    int y0 = max(0, cy-1), y1 = min(GRID-1, cy+1);
    for (int yy = y0; yy <= y1; yy++)
        for (int xx = x0; xx <= x1; xx++)
            scan_cell(b, yy*GRID + xx, q.x, q.y, bd, bi);
    const float hcell = 1.0f / GRID;
    int r = 1;
    while (true) {
        float bound = r * hcell;
        if (bd[3] <= bound*bound) break;
        bool full = (cx-r <= 0) && (cy-r <= 0) && (cx+r >= GRID-1) && (cy+r >= GRID-1);
        if (full) break;
        r++;
        int rx0 = cx-r, rx1 = cx+r, ry0 = cy-r, ry1 = cy+r;
        int cxl = max(0, rx0), cxr = min(GRID-1, rx1);
        if (ry0 >= 0)      for (int xx = cxl; xx <= cxr; xx++) scan_cell(b, ry0*GRID + xx, q.x, q.y, bd, bi);
        if (ry1 <= GRID-1) for (int xx = cxl; xx <= cxr; xx++) scan_cell(b, ry1*GRID + xx, q.x, q.y, bd, bi);
        int cyl = max(0, ry0+1), cyr = min(GRID-1, ry1-1);
        if (rx0 >= 0)      for (int yy = cyl; yy <= cyr; yy++) scan_cell(b, yy*GRID + rx0, q.x, q.y, bd, bi);
        if (rx1 <= GRID-1) for (int yy = cyl; yy <= cyr; yy++) scan_cell(b, yy*GRID + rx1, q.x, q.y, bd, bi);
    }
    #pragma unroll
    for (int k = 0; k < KNN; k++) d_nbr[n*KNN + k] = bi[k];
}

// ---------------- permute x into sorted order + fp16 convert -------------------
__global__ void perm_kernel(const float* __restrict__ x, __half* __restrict__ xp) {
    int w = (blockIdx.x * blockDim.x + threadIdx.x) >> 5;
    int lane = threadIdx.x & 31;
    if (w >= NTOT) return;
    int orig = ((w >> 13) << 13) + d_sorted[w];
    const float4* src = (const float4*)(x + (size_t)orig*CDIM);
    float4 v0 = src[lane*2], v1 = src[lane*2 + 1];
    __half2 h0 = __floats2half2_rn(v0.x, v0.y);
    __half2 h1 = __floats2half2_rn(v0.z, v0.w);
    __half2 h2 = __floats2half2_rn(v1.x, v1.y);
    __half2 h3 = __floats2half2_rn(v1.z, v1.w);
    uint4 o;
    o.x = *(uint32_t*)&h0; o.y = *(uint32_t*)&h1;
    o.z = *(uint32_t*)&h2; o.w = *(uint32_t*)&h3;
    *(uint4*)(xp + (size_t)w*CDIM + lane*8) = o;
}

// ------------------- W pack: fp32 [k][n] -> half2 [k2][n] ----------------------
__global__ void wprep_kernel(const float* __restrict__ W, uint32_t* __restrict__ Wp) {
    int i = blockIdx.x * blockDim.x + threadIdx.x;
    if (i >= 128*256) return;
    int k2 = i >> 8, n = i & 255;
    __half2 v = __floats2half2_rn(W[(2*k2)*CDIM + n], W[(2*k2+1)*CDIM + n]);
    Wp[i] = *(uint32_t*)&v;
}

__global__ void zero_att_kernel() {
    int i = blockIdx.x * blockDim.x + threadIdx.x;
    if (i < NTOT*HEADS) { d_as[i] = 0.f; d_ad[i] = 0.f; }
}

// --------------- fp16 persistent-W GEMM + fused attention scalars --------------
// grid (148, 2): blockIdx.y = column half (128 cols of W in smem),
// blockIdx.x strides row tiles of 128. A streamed via cp.async double buffer.
#define NS2 132                       // W smem stride (half2 units)
#define AS2 20                        // A smem stride (half2 units)
#define W_SMEM_H2 (128*NS2)           // 16896
#define A_SMEM_H2 (128*AS2)           // 2560
#define GEMM_SMEM ((W_SMEM_H2 + 2*A_SMEM_H2)*4)   // 88064 bytes

__global__ void __launch_bounds__(256, 2) gemm_f16_kernel(
    const __half* __restrict__ A, const uint32_t* __restrict__ Wp,
    const float* __restrict__ asrc, const float* __restrict__ adst,
    float* __restrict__ Hout, float* __restrict__ asb, float* __restrict__ adb)
{
    extern __shared__ uint32_t sm2[];
    uint32_t* Ws = sm2;
    uint32_t* Ab0 = sm2 + W_SMEM_H2;
    uint32_t* Ab1 = sm2 + W_SMEM_H2 + A_SMEM_H2;
    uint32_t sbase = smem_u32(sm2);
    uint32_t abase0 = sbase + W_SMEM_H2*4;
    uint32_t abase1 = abase0 + A_SMEM_H2*4;

    int tid = threadIdx.x;
    int wid = tid >> 5, lane = tid & 31;
    int g = lane >> 2, t = lane & 3;
    int wm = wid & 1, wn = wid >> 1;          // 2(M) x 4(N) warps, warp tile 64x32
    int cHalf = blockIdx.y;
    int colBase = cHalf*128;

    // load W half into smem (once)
    for (int i = tid; i < 128*32; i += 256) {
        int k2 = i >> 5, n4 = i & 31;
        cp16(sbase + (uint32_t)(k2*NS2 + n4*4)*4, Wp + (size_t)k2*256 + colBase + n4*4);
    }
    CP_COMMIT();

    // per-thread attention weights (8 cols each for src/dst)
    float sa0[4], sa1[4], sd0[4], sd1[4];
    #pragma unroll
    for (int nt = 0; nt < 4; nt++) {
        int col = colBase + wn*32 + nt*8 + t*2;
        sa0[nt] = asrc[col]; sa1[nt] = asrc[col+1];
        sd0[nt] = adst[col]; sd1[nt] = adst[col+1];
    }
    int hHead = (colBase + wn*32) >> 6;

    int ntiles = (1024 - blockIdx.x + 147) / 148;
    int nchunks = ntiles * 8;

    auto issue = [&](int c) {
        int rt = blockIdx.x + (c >> 3)*148;
        int kk = c & 7;
        const __half* src = A + (size_t)rt*128*CDIM + kk*32;
        uint32_t dstb = (c & 1) ? abase1 : abase0;
        #pragma unroll
        for (int i = 0; i < 2; i++) {
            int idx = tid + i*256;
            int r = idx >> 2, c4 = idx & 3;
            cp16(dstb + (uint32_t)(r*AS2 + c4*4)*4, src + (size_t)r*CDIM + c4*8);
        }
        CP_COMMIT();
    };

    float acc[4][4][4];
    #pragma unroll
    for (int mt = 0; mt < 4; mt++)
        #pragma unroll
        for (int nt = 0; nt < 4; nt++)
            #pragma unroll
            for (int i = 0; i < 4; i++) acc[mt][nt][i] = 0.f;

    issue(0);
    if (nchunks > 1) issue(1);

    #pragma unroll 1
    for (int c = 0; c < nchunks; c++) {
        if (c + 1 < nchunks) { CP_WAIT(1); } else { CP_WAIT(0); }
        __syncthreads();
        int kk = c & 7;
        const uint32_t* Abuf = (c & 1) ? Ab1 : Ab0;
        #pragma unroll
        for (int ks = 0; ks < 2; ks++) {
            int kh = ks*8;
            uint32_t af[4][4], bf[4][2];
            #pragma unroll
            for (int mt = 0; mt < 4; mt++) {
                int m0 = wm*64 + mt*16 + g;
                af[mt][0] = Abuf[m0*AS2 + kh + t];
                af[mt][1] = Abuf[(m0+8)*AS2 + kh + t];
                af[mt][2] = Abuf[m0*AS2 + kh + t + 4];
                af[mt][3] = Abuf[(m0+8)*AS2 + kh + t + 4];
            }
            int k2g = kk*16 + kh + t;
            #pragma unroll
            for (int nt = 0; nt < 4; nt++) {
                int n0 = wn*32 + nt*8 + g;
                bf[nt][0] = Ws[k2g*NS2 + n0];
                bf[nt][1] = Ws[(k2g+4)*NS2 + n0];
            }
            #pragma unroll
            for (int mt = 0; mt < 4; mt++)
                #pragma unroll
                for (int nt = 0; nt < 4; nt++)
                    mma_f16(acc[mt][nt], af[mt], bf[nt]);
        }
        if (kk == 7) {
            // epilogue for this row tile
            int rt = blockIdx.x + (c >> 3)*148;
            int rowBase = rt*128;
            #pragma unroll
            for (int mt = 0; mt < 4; mt++) {
                int r0 = rowBase + wm*64 + mt*16 + g;
                int r1 = r0 + 8;
                float sl_s = 0.f, sh_s = 0.f, sl_d = 0.f, sh_d = 0.f;
                #pragma unroll
                for (int nt = 0; nt < 4; nt++) {
                    int col = colBase + wn*32 + nt*8 + t*2;
                    *(float2*)(Hout + (size_t)r0*CDIM + col) = make_float2(acc[mt][nt][0], acc[mt][nt][1]);
                    *(float2*)(Hout + (size_t)r1*CDIM + col) = make_float2(acc[mt][nt][2], acc[mt][nt][3]);
                    sl_s += acc[mt][nt][0]*sa0[nt] + acc[mt][nt][1]*sa1[nt];
                    sh_s += acc[mt][nt][2]*sa0[nt] + acc[mt][nt][3]*sa1[nt];
                    sl_d += acc[mt][nt][0]*sd0[nt] + acc[mt][nt][1]*sd1[nt];
                    sh_d += acc[mt][nt][2]*sd0[nt] + acc[mt][nt][3]*sd1[nt];
                    acc[mt][nt][0] = acc[mt][nt][1] = acc[mt][nt][2] = acc[mt][nt][3] = 0.f;
                }
                sl_s += __shfl_xor_sync(0xffffffffu, sl_s, 1);
                sl_s += __shfl_xor_sync(0xffffffffu, sl_s, 2);
                sh_s += __shfl_xor_sync(0xffffffffu, sh_s, 1);
                sh_s += __shfl_xor_sync(0xffffffffu, sh_s, 2);
                sl_d += __shfl_xor_sync(0xffffffffu, sl_d, 1);
                sl_d += __shfl_xor_sync(0xffffffffu, sl_d, 2);
                sh_d += __shfl_xor_sync(0xffffffffu, sh_d, 1);
                sh_d += __shfl_xor_sync(0xffffffffu, sh_d, 2);
                if (t == 0) {
                    atomicAdd(asb + (size_t)r0*HEADS + hHead, sl_s);
                    atomicAdd(adb + (size_t)r0*HEADS + hHead, sl_d);
                    atomicAdd(asb + (size_t)r1*HEADS + hHead, sh_s);
                    atomicAdd(adb + (size_t)r1*HEADS + hHead, sh_d);
                }
            }
        }
        __syncthreads();
        if (c + 2 < nchunks) issue(c + 2);
    }
}

// ---------------------- softmax-attention aggregation --------------------------
// mode 0: write fp16 to outH (feeds next fp16 GEMM); mode 1: write fp32 to outF
__global__ void agg_kernel(const float* __restrict__ Hbuf,
                           const float* __restrict__ bias,
                           __half* __restrict__ outH, float* __restrict__ outF,
                           int mode) {
    int tid = threadIdx.x;
    int n = blockIdx.x*4 + (tid >> 6);
    int t = tid & 63;
    int nb[4];
    #pragma unroll
    for (int k = 0; k < 4; k++) nb[k] = d_nbr[n*KNN + k];
    float alpha[4][4];
    #pragma unroll
    for (int h = 0; h < HEADS; h++) {
        float ad = d_ad[n*HEADS + h];
        float e[4], m = -1e30f;
        #pragma unroll
        for (int k = 0; k < 4; k++) {
            float v = d_as[nb[k]*HEADS + h] + ad;
            v = v > 0.f ? v : NEG_SLOPE * v;
            e[k] = v; m = fmaxf(m, v);
        }
        float s = 0.f;
        #pragma unroll
        for (int k = 0; k < 4; k++) { e[k] = __expf(e[k] - m); s += e[k]; }
        float inv = 1.f / s;
        #pragma unroll
        for (int k = 0; k < 4; k++) alpha[k][h] = e[k] * inv;
    }
    #pragma unroll
    for (int h = 0; h < HEADS; h++) {
        float acc = bias[h*FDIM + t];
        #pragma unroll
        for (int k = 0; k < 4; k++)
            acc += alpha[k][h] * Hbuf[(size_t)nb[k]*CDIM + h*FDIM + t];
        acc = acc > 0.f ? acc : (__expf(acc) - 1.f);   // elu
        if (mode == 0) outH[(size_t)n*CDIM + h*FDIM + t] = __float2half_rn(acc);
        else           outF[(size_t)n*CDIM + h*FDIM + t] = acc;
    }
}

// --------------------------- layer 2 (256 -> 2) --------------------------------
__global__ void l2gemm_kernel(const float* __restrict__ X,
                              const float* __restrict__ W2,
                              const float* __restrict__ as2,
                              const float* __restrict__ ad2) {
    int wid  = (blockIdx.x * blockDim.x + threadIdx.x) >> 5;
    int lane = threadIdx.x & 31;
    if (wid >= NTOT) return;
    const float4* xp = (const float4*)&X[(size_t)wid * CDIM];
    float x8[8];
    *(float4*)&x8[0] = xp[lane*2];  *(float4*)&x8[4] = xp[lane*2+1];
    float d0 = 0.f, d1 = 0.f;
    #pragma unroll
    for (int j = 0; j < 8; j++) {
        int f = lane*8 + j;
        d0 += x8[j] * W2[f*2];
        d1 += x8[j] * W2[f*2 + 1];
    }
    #pragma unroll
    for (int off = 16; off > 0; off >>= 1) {
        d0 += __shfl_down_sync(0xffffffffu, d0, off);
        d1 += __shfl_down_sync(0xffffffffu, d1, off);
    }
    if (lane == 0) {
        d_h2[wid*2]   = d0;
        d_h2[wid*2+1] = d1;
        d_a2s[wid] = d0*as2[0] + d1*as2[1];
        d_a2d[wid] = d0*ad2[0] + d1*ad2[1];
    }
}

__global__ void final_kernel(const float* __restrict__ b2, float* __restrict__ out) {
    int n = blockIdx.x * blockDim.x + threadIdx.x;
    if (n >= NTOT) return;
    int nb[4];
    #pragma unroll
    for (int k = 0; k < 4; k++) nb[k] = d_nbr[n*KNN + k];
    float ad = d_a2d[n];
    float e[4], m = -1e30f;
    #pragma unroll
    for (int k = 0; k < 4; k++) {
        float v = d_a2s[nb[k]] + ad;
        v = v > 0.f ? v : NEG_SLOPE * v;
        e[k] = v; m = fmaxf(m, v);
    }
    float s = 0.f;
    #pragma unroll
    for (int k = 0; k < 4; k++) { e[k] = __expf(e[k] - m); s += e[k]; }
    float inv = 1.f / s;
    float o0 = 0.f, o1 = 0.f;
    #pragma unroll
    for (int k = 0; k < 4; k++) {
        float a = e[k] * inv;
        o0 += a * d_h2[nb[k]*2];
        o1 += a * d_h2[nb[k]*2 + 1];
    }
    int orig = ((n >> 13) << 13) + d_sorted[n];
    out[orig*2]     = o0 + b2[0];
    out[orig*2 + 1] = o1 + b2[1];
}

// --------------------------------- launch --------------------------------------
extern "C" void kernel_launch(void* const* d_in, const int* in_sizes, int n_in,
                              void* d_out, int out_size) {
    const float* coords   = (const float*)d_in[0];
    const float* x        = (const float*)d_in[1];
    const float* W0       = (const float*)d_in[2];
    const float* att_src0 = (const float*)d_in[3];
    const float* att_dst0 = (const float*)d_in[4];
    const float* b0       = (const float*)d_in[5];
    const float* W1       = (const float*)d_in[6];
    const float* att_src1 = (const float*)d_in[7];
    const float* att_dst1 = (const float*)d_in[8];
    const float* b1       = (const float*)d_in[9];
    const float* W2       = (const float*)d_in[10];
    const float* att_src2 = (const float*)d_in[11];
    const float* att_dst2 = (const float*)d_in[12];
    const float* b2       = (const float*)d_in[13];
    float* out = (float*)d_out;

    float *hp, *yp, *asp, *adp;
    __half* ahp;
    uint32_t *wp0, *wp1;
    cudaGetSymbolAddress((void**)&hp,  d_h);
    cudaGetSymbolAddress((void**)&yp,  d_y);
    cudaGetSymbolAddress((void**)&ahp, d_ah);
    cudaGetSymbolAddress((void**)&asp, d_as);
    cudaGetSymbolAddress((void**)&adp, d_ad);
    cudaGetSymbolAddress((void**)&wp0, d_wp0);
    cudaGetSymbolAddress((void**)&wp1, d_wp1);

    cudaFuncSetAttribute(gemm_f16_kernel, cudaFuncAttributeMaxDynamicSharedMemorySize, GEMM_SMEM);

    // W packing (fp16, k-paired)
    wprep_kernel<<<128, 256>>>(W0, wp0);
    wprep_kernel<<<128, 256>>>(W1, wp1);

    // kNN graph build (sorted space)
    zero_cnt_kernel<<<64, 256>>>();
    count_kernel<<<512, 256>>>(coords);
    scan_kernel<<<BATCH, 1024>>>();
    scatter_kernel<<<512, 256>>>(coords);
    knn_kernel<<<512, 256>>>();

    // permute + fp16 convert x
    perm_kernel<<<NTOT/8, 256>>>(x, ahp);

    dim3 ggrid(148, 2);

    // Layer 0
    zero_att_kernel<<<NTOT*HEADS/256, 256>>>();
    gemm_f16_kernel<<<ggrid, 256, GEMM_SMEM>>>(ahp, wp0, att_src0, att_dst0, hp, asp, adp);
    agg_kernel<<<NTOT/4, 256>>>(hp, b0, ahp, yp, 0);   // fp16 out -> next GEMM

    // Layer 1
    zero_att_kernel<<<NTOT*HEADS/256, 256>>>();
    gemm_f16_kernel<<<ggrid, 256, GEMM_SMEM>>>(ahp, wp1, att_src1, att_dst1, hp, asp, adp);
    agg_kernel<<<NTOT/4, 256>>>(hp, b1, ahp, yp, 1);   // fp32 out -> l2gemm

    // Layer 2
    l2gemm_kernel<<<NTOT/8, 256>>>(yp, W2, att_src2, att_dst2);
    final_kernel<<<512, 256>>>(b2, out);
}

// round 6
// speedup vs baseline: 2.7401x; 1.5513x over previous
#include <cuda_runtime.h>
#include <cuda_fp16.h>
#include <cstdint>
#include <math.h>

#define BATCH 16
#define PP    8192
#define NTOT  (BATCH*PP)     // 131072
#define KNN   4
#define CDIM  256
#define HEADS 4
#define FDIM  64
#define GRID  32
#define NCELL (GRID*GRID)    // 1024
#define NEG_SLOPE 0.2f

// ------------------- scratch (__device__ globals, no mallocs) -------------------
__device__ int      d_cnt[BATCH*NCELL];
__device__ int      d_start[BATCH*(NCELL+1)];
__device__ int      d_cur[BATCH*NCELL];
__device__ int      d_sorted[NTOT];
__device__ float2   d_sc[NTOT];
__device__ int      d_nbr[NTOT*KNN];
__device__ __half   d_hh[NTOT*CDIM];     // GEMM output (fp16, sorted space)
__device__ __half   d_ah[NTOT*CDIM];     // fp16 GEMM input (perm x / layer-0 agg out)
__device__ float    d_as[NTOT*HEADS];
__device__ float    d_ad[NTOT*HEADS];
__device__ float    d_h2[NTOT*2];
__device__ float    d_a2s[NTOT];
__device__ float    d_a2d[NTOT];
__device__ uint32_t d_wp0[128*256];      // W0 packed: half2 pairs along k, [k2][n]
__device__ uint32_t d_wp1[128*256];

// ----------------------------- PTX helpers --------------------------------------
__device__ __forceinline__ uint32_t smem_u32(const void* p) {
    uint32_t a;
    asm("{ .reg .u64 t; cvta.to.shared.u64 t, %1; cvt.u32.u64 %0, t; }" : "=r"(a) : "l"(p));
    return a;
}
__device__ __forceinline__ void cp16(uint32_t dst, const void* src) {
    asm volatile("cp.async.cg.shared.global [%0], [%1], 16;" :: "r"(dst), "l"(src));
}
#define CP_COMMIT() asm volatile("cp.async.commit_group;" ::: "memory")
#define CP_WAIT(N)  asm volatile("cp.async.wait_group %0;" :: "n"(N) : "memory")

__device__ __forceinline__ void mma_f16(float d[4], const uint32_t a[4], const uint32_t b[2]) {
    asm volatile(
        "mma.sync.aligned.m16n8k16.row.col.f32.f16.f16.f32 "
        "{%0,%1,%2,%3}, {%4,%5,%6,%7}, {%8,%9}, {%0,%1,%2,%3};"
        : "+f"(d[0]), "+f"(d[1]), "+f"(d[2]), "+f"(d[3])
        : "r"(a[0]), "r"(a[1]), "r"(a[2]), "r"(a[3]), "r"(b[0]), "r"(b[1]));
}

// ------------------------------- kNN pipeline ----------------------------------
__global__ void zero_cnt_kernel() {
    int i = blockIdx.x * blockDim.x + threadIdx.x;
    if (i < BATCH*NCELL) d_cnt[i] = 0;
}
__device__ __forceinline__ int cell_of(float v) {
    int c = (int)(v * GRID);
    return min(GRID-1, max(0, c));
}
__global__ void count_kernel(const float* __restrict__ coords) {
    int i = blockIdx.x * blockDim.x + threadIdx.x;
    if (i >= NTOT) return;
    float2 c = ((const float2*)coords)[i];
    int b = i >> 13;
    atomicAdd(&d_cnt[b*NCELL + cell_of(c.y)*GRID + cell_of(c.x)], 1);
}
__global__ void scan_kernel() {
    __shared__ int s[NCELL];
    int b = blockIdx.x, t = threadIdx.x;
    int v = d_cnt[b*NCELL + t];
    s[t] = v;
    __syncthreads();
    for (int off = 1; off < NCELL; off <<= 1) {
        int add = (t >= off) ? s[t-off] : 0;
        __syncthreads();
        s[t] += add;
        __syncthreads();
    }
    int excl = s[t] - v;
    d_start[b*(NCELL+1) + t] = excl;
    d_cur[b*NCELL + t]       = excl;
    if (t == NCELL-1) d_start[b*(NCELL+1) + NCELL] = s[t];
}
__global__ void scatter_kernel(const float* __restrict__ coords) {
    int i = blockIdx.x * blockDim.x + threadIdx.x;
    if (i >= NTOT) return;
    float2 c = ((const float2*)coords)[i];
    int b = i >> 13, p = i & (PP-1);
    int cell = cell_of(c.y)*GRID + cell_of(c.x);
    int pos = atomicAdd(&d_cur[b*NCELL + cell], 1);
    d_sorted[b*PP + pos] = p;
    d_sc[b*PP + pos] = c;
}
__device__ __forceinline__ void scan_cell(int b, int cell, float qx, float qy,
                                          float bd[4], int bi[4]) {
    int s0 = d_start[b*(NCELL+1) + cell];
    int s1 = d_start[b*(NCELL+1) + cell + 1];
    int base = b << 13;
    for (int j = s0; j < s1; j++) {
        float2 c2 = d_sc[base + j];
        float dx = c2.x - qx, dy = c2.y - qy;
        float d2 = dx*dx + dy*dy;
        if (d2 < bd[3]) {
            int gi = base + j;
            if (d2 < bd[2]) { bd[3]=bd[2]; bi[3]=bi[2];
                if (d2 < bd[1]) { bd[2]=bd[1]; bi[2]=bi[1];
                    if (d2 < bd[0]) { bd[1]=bd[0]; bi[1]=bi[0]; bd[0]=d2; bi[0]=gi; }
                    else            { bd[1]=d2; bi[1]=gi; }
                } else { bd[2]=d2; bi[2]=gi; }
            } else { bd[3]=d2; bi[3]=gi; }
        }
    }
}
__global__ void knn_kernel() {
    int n = blockIdx.x * blockDim.x + threadIdx.x;
    if (n >= NTOT) return;
    int b = n >> 13;
    float2 q = d_sc[n];
    int cx = cell_of(q.x), cy = cell_of(q.y);
    float bd[4] = {1e30f, 1e30f, 1e30f, 1e30f};
    int   bi[4] = {n, n, n, n};
    int x0 = max(0, cx-1), x1 = min(GRID-1, cx+1);
    int y0 = max(0, cy-1), y1 = min(GRID-1, cy+1);
    for (int yy = y0; yy <= y1; yy++)
        for (int xx = x0; xx <= x1; xx++)
            scan_cell(b, yy*GRID + xx, q.x, q.y, bd, bi);
    const float hcell = 1.0f / GRID;
    int r = 1;
    while (true) {
        float bound = r * hcell;
        if (bd[3] <= bound*bound) break;
        bool full = (cx-r <= 0) && (cy-r <= 0) && (cx+r >= GRID-1) && (cy+r >= GRID-1);
        if (full) break;
        r++;
        int rx0 = cx-r, rx1 = cx+r, ry0 = cy-r, ry1 = cy+r;
        int cxl = max(0, rx0), cxr = min(GRID-1, rx1);
        if (ry0 >= 0)      for (int xx = cxl; xx <= cxr; xx++) scan_cell(b, ry0*GRID + xx, q.x, q.y, bd, bi);
        if (ry1 <= GRID-1) for (int xx = cxl; xx <= cxr; xx++) scan_cell(b, ry1*GRID + xx, q.x, q.y, bd, bi);
        int cyl = max(0, ry0+1), cyr = min(GRID-1, ry1-1);
        if (rx0 >= 0)      for (int yy = cyl; yy <= cyr; yy++) scan_cell(b, yy*GRID + rx0, q.x, q.y, bd, bi);
        if (rx1 <= GRID-1) for (int yy = cyl; yy <= cyr; yy++) scan_cell(b, yy*GRID + rx1, q.x, q.y, bd, bi);
    }
    #pragma unroll
    for (int k = 0; k < KNN; k++) d_nbr[n*KNN + k] = bi[k];
}

// ---------------- permute x into sorted order + fp16 convert -------------------
__global__ void perm_kernel(const float* __restrict__ x, __half* __restrict__ xp) {
    int w = (blockIdx.x * blockDim.x + threadIdx.x) >> 5;
    int lane = threadIdx.x & 31;
    if (w >= NTOT) return;
    int orig = ((w >> 13) << 13) + d_sorted[w];
    const float4* src = (const float4*)(x + (size_t)orig*CDIM);
    float4 v0 = src[lane*2], v1 = src[lane*2 + 1];
    __half2 h0 = __floats2half2_rn(v0.x, v0.y);
    __half2 h1 = __floats2half2_rn(v0.z, v0.w);
    __half2 h2 = __floats2half2_rn(v1.x, v1.y);
    __half2 h3 = __floats2half2_rn(v1.z, v1.w);
    uint4 o;
    o.x = *(uint32_t*)&h0; o.y = *(uint32_t*)&h1;
    o.z = *(uint32_t*)&h2; o.w = *(uint32_t*)&h3;
    *(uint4*)(xp + (size_t)w*CDIM + lane*8) = o;
}

// ------------------- W pack: fp32 [k][n] -> half2 [k2][n] ----------------------
__global__ void wprep_kernel(const float* __restrict__ W, uint32_t* __restrict__ Wp) {
    int i = blockIdx.x * blockDim.x + threadIdx.x;
    if (i >= 128*256) return;
    int k2 = i >> 8, n = i & 255;
    __half2 v = __floats2half2_rn(W[(2*k2)*CDIM + n], W[(2*k2+1)*CDIM + n]);
    Wp[i] = *(uint32_t*)&v;
}

__global__ void zero_att_kernel() {
    int i = blockIdx.x * blockDim.x + threadIdx.x;
    if (i < NTOT*HEADS) { d_as[i] = 0.f; d_ad[i] = 0.f; }
}

// --------------- fp16 persistent-W GEMM + fused attention scalars --------------
#define NS2 132
#define AS2 20
#define W_SMEM_H2 (128*NS2)
#define A_SMEM_H2 (128*AS2)
#define GEMM_SMEM ((W_SMEM_H2 + 2*A_SMEM_H2)*4)   // 88064 bytes

__global__ void __launch_bounds__(256, 2) gemm_f16_kernel(
    const __half* __restrict__ A, const uint32_t* __restrict__ Wp,
    const float* __restrict__ asrc, const float* __restrict__ adst,
    __half* __restrict__ Hout, float* __restrict__ asb, float* __restrict__ adb)
{
    extern __shared__ uint32_t sm2[];
    uint32_t* Ws = sm2;
    uint32_t* Ab0 = sm2 + W_SMEM_H2;
    uint32_t* Ab1 = sm2 + W_SMEM_H2 + A_SMEM_H2;
    uint32_t sbase = smem_u32(sm2);
    uint32_t abase0 = sbase + W_SMEM_H2*4;
    uint32_t abase1 = abase0 + A_SMEM_H2*4;

    int tid = threadIdx.x;
    int wid = tid >> 5, lane = tid & 31;
    int g = lane >> 2, t = lane & 3;
    int wm = wid & 1, wn = wid >> 1;
    int cHalf = blockIdx.y;
    int colBase = cHalf*128;

    for (int i = tid; i < 128*32; i += 256) {
        int k2 = i >> 5, n4 = i & 31;
        cp16(sbase + (uint32_t)(k2*NS2 + n4*4)*4, Wp + (size_t)k2*256 + colBase + n4*4);
    }
    CP_COMMIT();

    float sa0[4], sa1[4], sd0[4], sd1[4];
    #pragma unroll
    for (int nt = 0; nt < 4; nt++) {
        int col = colBase + wn*32 + nt*8 + t*2;
        sa0[nt] = asrc[col]; sa1[nt] = asrc[col+1];
        sd0[nt] = adst[col]; sd1[nt] = adst[col+1];
    }
    int hHead = (colBase + wn*32) >> 6;

    int ntiles = (1024 - blockIdx.x + 147) / 148;
    int nchunks = ntiles * 8;

    auto issue = [&](int c) {
        int rt = blockIdx.x + (c >> 3)*148;
        int kk = c & 7;
        const __half* src = A + (size_t)rt*128*CDIM + kk*32;
        uint32_t dstb = (c & 1) ? abase1 : abase0;
        #pragma unroll
        for (int i = 0; i < 2; i++) {
            int idx = tid + i*256;
            int r = idx >> 2, c4 = idx & 3;
            cp16(dstb + (uint32_t)(r*AS2 + c4*4)*4, src + (size_t)r*CDIM + c4*8);
        }
        CP_COMMIT();
    };

    float acc[4][4][4];
    #pragma unroll
    for (int mt = 0; mt < 4; mt++)
        #pragma unroll
        for (int nt = 0; nt < 4; nt++)
            #pragma unroll
            for (int i = 0; i < 4; i++) acc[mt][nt][i] = 0.f;

    issue(0);
    if (nchunks > 1) issue(1);

    #pragma unroll 1
    for (int c = 0; c < nchunks; c++) {
        if (c + 1 < nchunks) { CP_WAIT(1); } else { CP_WAIT(0); }
        __syncthreads();
        int kk = c & 7;
        const uint32_t* Abuf = (c & 1) ? Ab1 : Ab0;
        #pragma unroll
        for (int ks = 0; ks < 2; ks++) {
            int kh = ks*8;
            uint32_t af[4][4], bf[4][2];
            #pragma unroll
            for (int mt = 0; mt < 4; mt++) {
                int m0 = wm*64 + mt*16 + g;
                af[mt][0] = Abuf[m0*AS2 + kh + t];
                af[mt][1] = Abuf[(m0+8)*AS2 + kh + t];
                af[mt][2] = Abuf[m0*AS2 + kh + t + 4];
                af[mt][3] = Abuf[(m0+8)*AS2 + kh + t + 4];
            }
            int k2g = kk*16 + kh + t;
            #pragma unroll
            for (int nt = 0; nt < 4; nt++) {
                int n0 = wn*32 + nt*8 + g;
                bf[nt][0] = Ws[k2g*NS2 + n0];
                bf[nt][1] = Ws[(k2g+4)*NS2 + n0];
            }
            #pragma unroll
            for (int mt = 0; mt < 4; mt++)
                #pragma unroll
                for (int nt = 0; nt < 4; nt++)
                    mma_f16(acc[mt][nt], af[mt], bf[nt]);
        }
        if (kk == 7) {
            int rt = blockIdx.x + (c >> 3)*148;
            int rowBase = rt*128;
            #pragma unroll
            for (int mt = 0; mt < 4; mt++) {
                int r0 = rowBase + wm*64 + mt*16 + g;
                int r1 = r0 + 8;
                float sl_s = 0.f, sh_s = 0.f, sl_d = 0.f, sh_d = 0.f;
                #pragma unroll
                for (int nt = 0; nt < 4; nt++) {
                    int col = colBase + wn*32 + nt*8 + t*2;
                    *(__half2*)(Hout + (size_t)r0*CDIM + col) = __floats2half2_rn(acc[mt][nt][0], acc[mt][nt][1]);
                    *(__half2*)(Hout + (size_t)r1*CDIM + col) = __floats2half2_rn(acc[mt][nt][2], acc[mt][nt][3]);
                    sl_s += acc[mt][nt][0]*sa0[nt] + acc[mt][nt][1]*sa1[nt];
                    sh_s += acc[mt][nt][2]*sa0[nt] + acc[mt][nt][3]*sa1[nt];
                    sl_d += acc[mt][nt][0]*sd0[nt] + acc[mt][nt][1]*sd1[nt];
                    sh_d += acc[mt][nt][2]*sd0[nt] + acc[mt][nt][3]*sd1[nt];
                    acc[mt][nt][0] = acc[mt][nt][1] = acc[mt][nt][2] = acc[mt][nt][3] = 0.f;
                }
                sl_s += __shfl_xor_sync(0xffffffffu, sl_s, 1);
                sl_s += __shfl_xor_sync(0xffffffffu, sl_s, 2);
                sh_s += __shfl_xor_sync(0xffffffffu, sh_s, 1);
                sh_s += __shfl_xor_sync(0xffffffffu, sh_s, 2);
                sl_d += __shfl_xor_sync(0xffffffffu, sl_d, 1);
                sl_d += __shfl_xor_sync(0xffffffffu, sl_d, 2);
                sh_d += __shfl_xor_sync(0xffffffffu, sh_d, 1);
                sh_d += __shfl_xor_sync(0xffffffffu, sh_d, 2);
                if (t == 0) {
                    atomicAdd(asb + (size_t)r0*HEADS + hHead, sl_s);
                    atomicAdd(adb + (size_t)r0*HEADS + hHead, sl_d);
                    atomicAdd(asb + (size_t)r1*HEADS + hHead, sh_s);
                    atomicAdd(adb + (size_t)r1*HEADS + hHead, sh_d);
                }
            }
        }
        __syncthreads();
        if (c + 2 < nchunks) issue(c + 2);
    }
}

// ---------------------- softmax-attention aggregation --------------------------
// one warp per node; lane handles feature pair (2*lane, 2*lane+1) of each head.
// mode 0: write fp16 (next GEMM input).  mode 1: fused layer-2 (no feature write).
__global__ void agg_kernel(const __half* __restrict__ Hbuf,
                           const float* __restrict__ bias,
                           __half* __restrict__ outH,
                           const float* __restrict__ W2,
                           const float* __restrict__ as2,
                           const float* __restrict__ ad2,
                           int mode) {
    int w = (blockIdx.x * blockDim.x + threadIdx.x) >> 5;
    int lane = threadIdx.x & 31;
    if (w >= NTOT) return;
    int nb[4];
    #pragma unroll
    for (int k = 0; k < 4; k++) nb[k] = d_nbr[w*KNN + k];
    float alpha[4][4];   // [k][h]
    #pragma unroll
    for (int h = 0; h < HEADS; h++) {
        float ad = d_ad[w*HEADS + h];
        float e[4], m = -1e30f;
        #pragma unroll
        for (int k = 0; k < 4; k++) {
            float v = d_as[nb[k]*HEADS + h] + ad;
            v = v > 0.f ? v : NEG_SLOPE * v;
            e[k] = v; m = fmaxf(m, v);
        }
        float s = 0.f;
        #pragma unroll
        for (int k = 0; k < 4; k++) { e[k] = __expf(e[k] - m); s += e[k]; }
        float inv = 1.f / s;
        #pragma unroll
        for (int k = 0; k < 4; k++) alpha[k][h] = e[k] * inv;
    }
    float d0 = 0.f, d1 = 0.f;
    #pragma unroll
    for (int h = 0; h < HEADS; h++) {
        int f = h*FDIM + 2*lane;
        float ax = bias[f], ay = bias[f+1];
        #pragma unroll
        for (int k = 0; k < 4; k++) {
            __half2 hv = *(const __half2*)(Hbuf + (size_t)nb[k]*CDIM + f);
            float2 fv = __half22float2(hv);
            ax += alpha[k][h] * fv.x;
            ay += alpha[k][h] * fv.y;
        }
        ax = ax > 0.f ? ax : (__expf(ax) - 1.f);
        ay = ay > 0.f ? ay : (__expf(ay) - 1.f);
        if (mode == 0) {
            *(__half2*)(outH + (size_t)w*CDIM + f) = __floats2half2_rn(ax, ay);
        } else {
            float4 wv = *(const float4*)(W2 + f*2);
            d0 += ax*wv.x + ay*wv.z;
            d1 += ax*wv.y + ay*wv.w;
        }
    }
    if (mode == 1) {
        #pragma unroll
        for (int off = 16; off > 0; off >>= 1) {
            d0 += __shfl_xor_sync(0xffffffffu, d0, off);
            d1 += __shfl_xor_sync(0xffffffffu, d1, off);
        }
        if (lane == 0) {
            d_h2[w*2]   = d0;
            d_h2[w*2+1] = d1;
            d_a2s[w] = d0*as2[0] + d1*as2[1];
            d_a2d[w] = d0*ad2[0] + d1*ad2[1];
        }
    }
}

__global__ void final_kernel(const float* __restrict__ b2, float* __restrict__ out) {
    int n = blockIdx.x * blockDim.x + threadIdx.x;
    if (n >= NTOT) return;
    int nb[4];
    #pragma unroll
    for (int k = 0; k < 4; k++) nb[k] = d_nbr[n*KNN + k];
    float ad = d_a2d[n];
    float e[4], m = -1e30f;
    #pragma unroll
    for (int k = 0; k < 4; k++) {
        float v = d_a2s[nb[k]] + ad;
        v = v > 0.f ? v : NEG_SLOPE * v;
        e[k] = v; m = fmaxf(m, v);
    }
    float s = 0.f;
    #pragma unroll
    for (int k = 0; k < 4; k++) { e[k] = __expf(e[k] - m); s += e[k]; }
    float inv = 1.f / s;
    float o0 = 0.f, o1 = 0.f;
    #pragma unroll
    for (int k = 0; k < 4; k++) {
        float a = e[k] * inv;
        o0 += a * d_h2[nb[k]*2];
        o1 += a * d_h2[nb[k]*2 + 1];
    }
    int orig = ((n >> 13) << 13) + d_sorted[n];
    out[orig*2]     = o0 + b2[0];
    out[orig*2 + 1] = o1 + b2[1];
}

// --------------------------------- launch --------------------------------------
extern "C" void kernel_launch(void* const* d_in, const int* in_sizes, int n_in,
                              void* d_out, int out_size) {
    const float* coords   = (const float*)d_in[0];
    const float* x        = (const float*)d_in[1];
    const float* W0       = (const float*)d_in[2];
    const float* att_src0 = (const float*)d_in[3];
    const float* att_dst0 = (const float*)d_in[4];
    const float* b0       = (const float*)d_in[5];
    const float* W1       = (const float*)d_in[6];
    const float* att_src1 = (const float*)d_in[7];
    const float* att_dst1 = (const float*)d_in[8];
    const float* b1       = (const float*)d_in[9];
    const float* W2       = (const float*)d_in[10];
    const float* att_src2 = (const float*)d_in[11];
    const float* att_dst2 = (const float*)d_in[12];
    const float* b2       = (const float*)d_in[13];
    float* out = (float*)d_out;

    float *asp, *adp;
    __half *ahp, *hhp;
    uint32_t *wp0, *wp1;
    cudaGetSymbolAddress((void**)&hhp, d_hh);
    cudaGetSymbolAddress((void**)&ahp, d_ah);
    cudaGetSymbolAddress((void**)&asp, d_as);
    cudaGetSymbolAddress((void**)&adp, d_ad);
    cudaGetSymbolAddress((void**)&wp0, d_wp0);
    cudaGetSymbolAddress((void**)&wp1, d_wp1);

    cudaFuncSetAttribute(gemm_f16_kernel, cudaFuncAttributeMaxDynamicSharedMemorySize, GEMM_SMEM);

    // W packing (fp16, k-paired)
    wprep_kernel<<<128, 256>>>(W0, wp0);
    wprep_kernel<<<128, 256>>>(W1, wp1);

    // kNN graph build (sorted space)
    zero_cnt_kernel<<<64, 256>>>();
    count_kernel<<<512, 256>>>(coords);
    scan_kernel<<<BATCH, 1024>>>();
    scatter_kernel<<<512, 256>>>(coords);
    knn_kernel<<<512, 256>>>();

    // permute + fp16 convert x
    perm_kernel<<<NTOT/8, 256>>>(x, ahp);

    dim3 ggrid(148, 2);

    // Layer 0
    zero_att_kernel<<<NTOT*HEADS/256, 256>>>();
    gemm_f16_kernel<<<ggrid, 256, GEMM_SMEM>>>(ahp, wp0, att_src0, att_dst0, hhp, asp, adp);
    agg_kernel<<<NTOT/8, 256>>>(hhp, b0, ahp, nullptr, nullptr, nullptr, 0);

    // Layer 1 (+ fused layer-2 projection in agg)
    zero_att_kernel<<<NTOT*HEADS/256, 256>>>();
    gemm_f16_kernel<<<ggrid, 256, GEMM_SMEM>>>(ahp, wp1, att_src1, att_dst1, hhp, asp, adp);
    agg_kernel<<<NTOT/8, 256>>>(hhp, b1, nullptr, W2, att_src2, att_dst2, 1);

    // Final attention layer
    final_kernel<<<512, 256>>>(b2, out);
}